// round 6
// baseline (speedup 1.0000x reference)
#include <cuda_runtime.h>

// PlaneEmbeddingNetwork, R6: 3-kernel pipeline with cooperative gather.
// K1: per-node qkv -> g_qkv[node][head][32f] (rows padded to one 128B line)
// K2: per-(face,head) attention + fused-W2 + relu + pool. The random gather is
//     done cooperatively: each LDG.128 instruction covers 4 whole rows (4 wf
//     instead of 32), staged through XOR-swizzled smem (4-wf optimal both ways).
//     Pooled output written TRANSPOSED g_poolT[k][face] for coalesced fco.
// K3: fco GEMM, thread = 4 faces x 16 cols, inputs via coalesced poolT loads.

typedef unsigned long long u64;

__device__ __forceinline__ u64 fma2(u64 a, u64 b, u64 c) {
    u64 d;
    asm("fma.rn.f32x2 %0, %1, %2, %3;" : "=l"(d) : "l"(a), "l"(b), "l"(c));
    return d;
}
__device__ __forceinline__ u64 pack2(float x, float y) {
    u64 r;
    asm("mov.b64 %0, {%1, %2};" : "=l"(r) : "f"(x), "f"(y));
    return r;
}
__device__ __forceinline__ float2 unpack2(u64 v) {
    float2 f;
    asm("mov.b64 {%0, %1}, %2;" : "=f"(f.x), "=f"(f.y) : "l"(v));
    return f;
}
__device__ __forceinline__ float getc(float4 v, int c) {
    return c == 0 ? v.x : (c == 1 ? v.y : (c == 2 ? v.z : v.w));
}

// Static scratch (allocation-free rule).
__device__ __align__(256) float g_qkv[250000 * 64];    // [node][h][q8,k8,v8,pad8]
__device__ __align__(16) float g_poolT[32 * 500000];   // [k][face]
__device__ __align__(16) float g_W2f[512];             // fused w_out @ fc_w
__device__ __align__(16) float g_b2f[32];              // fc_b + b_out @ fc_w

// ---------------------------------------------------------------------------
__global__ void prep_kernel(const float* __restrict__ w_out, const float* __restrict__ b_out,
                            const float* __restrict__ fc_w, const float* __restrict__ fc_b) {
    int i = threadIdx.x;
    if (i < 512) {
        int d = i >> 5, j = i & 31;
        float s = 0.f;
#pragma unroll
        for (int e = 0; e < 16; e++) s += w_out[d * 16 + e] * fc_w[e * 32 + j];
        g_W2f[i] = s;
    }
    if (i < 32) {
        float s = fc_b[i];
#pragma unroll
        for (int e = 0; e < 16; e++) s += b_out[e] * fc_w[e * 32 + i];
        g_b2f[i] = s;
    }
}

// ---------------------------------------------------------------------------
// K1: thread = (node-pair, head). qkv (own head, 24 cols) for 2 nodes.
__global__ void __launch_bounds__(128)
qkv_kernel(const float* __restrict__ node, const float* __restrict__ w_in,
           const float* __restrict__ b_in, int Nn) {
    __shared__ __align__(16) float s_w[768];
    __shared__ __align__(16) float s_b[48];
    int tid = threadIdx.x;
    for (int i = tid; i < 768; i += 128) s_w[i] = w_in[i];
    if (tid < 48) s_b[tid] = b_in[tid];
    __syncthreads();

    int gi = blockIdx.x * 128 + tid;
    int h = gi & 1;
    int g = gi >> 1;
    int npairs = Nn >> 1;
    bool valid = g < npairs;
    if (!valid) g = npairs - 1;
    int n0 = 2 * g, n1 = 2 * g + 1;

    float4 X0[4], X1[4];
    {
        const float4* r0 = (const float4*)(node + 16ll * n0);
        const float4* r1 = (const float4*)(node + 16ll * n1);
        X0[0] = r0[0]; X0[1] = r0[1]; X0[2] = r0[2]; X0[3] = r0[3];
        X1[0] = r1[0]; X1[1] = r1[1]; X1[2] = r1[2]; X1[3] = r1[3];
    }

    u64 a0[12], a1[12];   // [q0..3, k0..3, v0..3]
    {
        const u64* bq = (const u64*)(s_b + 8 * h);
        const u64* bk = (const u64*)(s_b + 16 + 8 * h);
        const u64* bv = (const u64*)(s_b + 32 + 8 * h);
#pragma unroll
        for (int j = 0; j < 4; j++) {
            a0[j] = bq[j];     a1[j] = bq[j];
            a0[4 + j] = bk[j]; a1[4 + j] = bk[j];
            a0[8 + j] = bv[j]; a1[8 + j] = bv[j];
        }
    }
#pragma unroll
    for (int d = 0; d < 16; d++) {
        const float* w = s_w + d * 48 + 8 * h;
        ulonglong2 wqa = *(const ulonglong2*)(w);
        ulonglong2 wqb = *(const ulonglong2*)(w + 4);
        ulonglong2 wka = *(const ulonglong2*)(w + 16);
        ulonglong2 wkb = *(const ulonglong2*)(w + 20);
        ulonglong2 wva = *(const ulonglong2*)(w + 32);
        ulonglong2 wvb = *(const ulonglong2*)(w + 36);
        float x0 = getc(X0[d >> 2], d & 3);
        float x1 = getc(X1[d >> 2], d & 3);
        u64 p0 = pack2(x0, x0), p1 = pack2(x1, x1);
        a0[0] = fma2(p0, wqa.x, a0[0]);  a0[1] = fma2(p0, wqa.y, a0[1]);
        a0[2] = fma2(p0, wqb.x, a0[2]);  a0[3] = fma2(p0, wqb.y, a0[3]);
        a0[4] = fma2(p0, wka.x, a0[4]);  a0[5] = fma2(p0, wka.y, a0[5]);
        a0[6] = fma2(p0, wkb.x, a0[6]);  a0[7] = fma2(p0, wkb.y, a0[7]);
        a0[8] = fma2(p0, wva.x, a0[8]);  a0[9] = fma2(p0, wva.y, a0[9]);
        a0[10] = fma2(p0, wvb.x, a0[10]); a0[11] = fma2(p0, wvb.y, a0[11]);
        a1[0] = fma2(p1, wqa.x, a1[0]);  a1[1] = fma2(p1, wqa.y, a1[1]);
        a1[2] = fma2(p1, wqb.x, a1[2]);  a1[3] = fma2(p1, wqb.y, a1[3]);
        a1[4] = fma2(p1, wka.x, a1[4]);  a1[5] = fma2(p1, wka.y, a1[5]);
        a1[6] = fma2(p1, wkb.x, a1[6]);  a1[7] = fma2(p1, wkb.y, a1[7]);
        a1[8] = fma2(p1, wva.x, a1[8]);  a1[9] = fma2(p1, wva.y, a1[9]);
        a1[10] = fma2(p1, wvb.x, a1[10]); a1[11] = fma2(p1, wvb.y, a1[11]);
    }

    if (valid) {
        float* o0 = g_qkv + (size_t)n0 * 64 + h * 32;
        float* o1 = g_qkv + (size_t)n1 * 64 + h * 32;
#pragma unroll
        for (int j = 0; j < 6; j++) {
            float2 x = unpack2(a0[2 * j]), y = unpack2(a0[2 * j + 1]);
            ((float4*)o0)[j] = make_float4(x.x, x.y, y.x, y.y);
        }
        ((float4*)o0)[6] = make_float4(0.f, 0.f, 0.f, 0.f);
        ((float4*)o0)[7] = make_float4(0.f, 0.f, 0.f, 0.f);
#pragma unroll
        for (int j = 0; j < 6; j++) {
            float2 x = unpack2(a1[2 * j]), y = unpack2(a1[2 * j + 1]);
            ((float4*)o1)[j] = make_float4(x.x, x.y, y.x, y.y);
        }
        ((float4*)o1)[6] = make_float4(0.f, 0.f, 0.f, 0.f);
        ((float4*)o1)[7] = make_float4(0.f, 0.f, 0.f, 0.f);
    }
}

// ---------------------------------------------------------------------------
// K2: block = 64 faces x 2 heads. Cooperative per-token gather via smem.
// XOR-swizzled stage: float offset = r*32 + ((c ^ (r&7)) << 2).
__global__ void __launch_bounds__(128)
face_kernel(const int* __restrict__ fids, int F) {
    __shared__ __align__(16) float s_stage[128 * 32];  // 16 KB
    __shared__ int s_id[4 * 64];
    __shared__ __align__(16) float sW2[512];
    __shared__ __align__(16) float sb2[32];

    int tid = threadIdx.x;
    for (int i = tid; i < 512; i += 128) sW2[i] = g_W2f[i];
    if (tid < 32) sb2[tid] = g_b2f[tid];

    int fl = tid >> 1;     // local face 0..63
    int h = tid & 1;       // head
    int face = blockIdx.x * 64 + fl;
    bool valid = face < F;
    if (!valid) face = F - 1;

    {
        int4 I = *(const int4*)(fids + 4ll * face);
        if (h == 0) {
            s_id[0 * 64 + fl] = I.x;
            s_id[1 * 64 + fl] = I.y;
            s_id[2 * 64 + fl] = I.z;
            s_id[3 * 64 + fl] = I.w;
        }
    }
    __syncthreads();

    int c = tid & 7;         // chunk this thread loads
    int rbase = tid >> 3;    // 0..15
    int myr = (fl << 1) | h; // my stage row
    int myb = myr * 32;
    int mys = myr & 7;

    u64 q2[4][4], k2[4][4], v2[4][4];
#pragma unroll
    for (int t = 0; t < 4; t++) {
        // cooperative load: 128 rows x 8 chunks; inst j covers 4 whole rows
#pragma unroll
        for (int j = 0; j < 8; j++) {
            int r = rbase + 16 * j;
            int f = r >> 1, hh = r & 1;
            int id = s_id[t * 64 + f];
            float4 v = *(const float4*)(g_qkv + (size_t)id * 64 + hh * 32 + c * 4);
            *(float4*)(s_stage + r * 32 + ((c ^ (r & 7)) << 2)) = v;
        }
        __syncthreads();
        // readback own row: chunks 0-5 = q8,k8,v8
        {
            ulonglong2 u0 = *(const ulonglong2*)(s_stage + myb + ((0 ^ mys) << 2));
            ulonglong2 u1 = *(const ulonglong2*)(s_stage + myb + ((1 ^ mys) << 2));
            ulonglong2 u2 = *(const ulonglong2*)(s_stage + myb + ((2 ^ mys) << 2));
            ulonglong2 u3 = *(const ulonglong2*)(s_stage + myb + ((3 ^ mys) << 2));
            ulonglong2 u4 = *(const ulonglong2*)(s_stage + myb + ((4 ^ mys) << 2));
            ulonglong2 u5 = *(const ulonglong2*)(s_stage + myb + ((5 ^ mys) << 2));
            q2[t][0] = u0.x; q2[t][1] = u0.y; q2[t][2] = u1.x; q2[t][3] = u1.y;
            k2[t][0] = u2.x; k2[t][1] = u2.y; k2[t][2] = u3.x; k2[t][3] = u3.y;
            v2[t][0] = u4.x; v2[t][1] = u4.y; v2[t][2] = u5.x; v2[t][3] = u5.y;
        }
        __syncthreads();
    }

    // scores + softmax (own head, 4x4)
    float att[4][4];
    const float RS = 0.35355339059327373f;  // 1/sqrt(8)
#pragma unroll
    for (int qi = 0; qi < 4; qi++) {
#pragma unroll
        for (int ki = 0; ki < 4; ki++) {
            u64 a = fma2(q2[qi][0], k2[ki][0], 0ull);
            a = fma2(q2[qi][1], k2[ki][1], a);
            a = fma2(q2[qi][2], k2[ki][2], a);
            a = fma2(q2[qi][3], k2[ki][3], a);
            float2 p = unpack2(a);
            att[qi][ki] = (p.x + p.y) * RS;
        }
        float m = fmaxf(fmaxf(att[qi][0], att[qi][1]), fmaxf(att[qi][2], att[qi][3]));
        float e0 = __expf(att[qi][0] - m);
        float e1 = __expf(att[qi][1] - m);
        float e2 = __expf(att[qi][2] - m);
        float e3 = __expf(att[qi][3] - m);
        float inv = 1.0f / (e0 + e1 + e2 + e3);
        att[qi][0] = e0 * inv; att[qi][1] = e1 * inv;
        att[qi][2] = e2 * inv; att[qi][3] = e3 * inv;
    }

    // o = attn @ v (own head 8 dims, 4 query tokens)
    u64 o2[4][4];
#pragma unroll
    for (int qi = 0; qi < 4; qi++) {
#pragma unroll
        for (int j = 0; j < 4; j++) o2[qi][j] = 0ull;
#pragma unroll
        for (int s = 0; s < 4; s++) {
            u64 a2 = pack2(att[qi][s], att[qi][s]);
#pragma unroll
            for (int j = 0; j < 4; j++) o2[qi][j] = fma2(a2, v2[s][j], o2[qi][j]);
        }
    }

    // exchange with partner lane (adjacent, other head): full 16-dim o per token
    u64 lo[4][4], hi[4][4];
#pragma unroll
    for (int t = 0; t < 4; t++)
#pragma unroll
        for (int j = 0; j < 4; j++) {
            u64 rcv = __shfl_xor_sync(0xffffffffu, o2[t][j], 1);
            lo[t][j] = h ? rcv : o2[t][j];
            hi[t][j] = h ? o2[t][j] : rcv;
        }

    // W2 col-split: this thread computes cols [16h,16h+16) for all 4 tokens
    u64 acc[4][8];
    {
        const u64* bb = (const u64*)(sb2 + 16 * h);
#pragma unroll
        for (int t = 0; t < 4; t++)
#pragma unroll
            for (int j = 0; j < 8; j++) acc[t][j] = bb[j];
    }
#pragma unroll
    for (int d = 0; d < 16; d++) {
        const ulonglong2* wr = (const ulonglong2*)(sW2 + d * 32 + 16 * h);
        ulonglong2 wa = wr[0], wb = wr[1], wc = wr[2], wd = wr[3];
#pragma unroll
        for (int t = 0; t < 4; t++) {
            float ov;
            if (d < 8) {
                float2 p = unpack2(lo[t][d >> 1]);
                ov = (d & 1) ? p.y : p.x;
            } else {
                float2 p = unpack2(hi[t][(d - 8) >> 1]);
                ov = (d & 1) ? p.y : p.x;
            }
            u64 op = pack2(ov, ov);
            acc[t][0] = fma2(op, wa.x, acc[t][0]);
            acc[t][1] = fma2(op, wa.y, acc[t][1]);
            acc[t][2] = fma2(op, wb.x, acc[t][2]);
            acc[t][3] = fma2(op, wb.y, acc[t][3]);
            acc[t][4] = fma2(op, wc.x, acc[t][4]);
            acc[t][5] = fma2(op, wc.y, acc[t][5]);
            acc[t][6] = fma2(op, wd.x, acc[t][6]);
            acc[t][7] = fma2(op, wd.y, acc[t][7]);
        }
    }

    // relu + mean over 4 tokens, write own 16 cols TRANSPOSED to g_poolT
    if (valid) {
#pragma unroll
        for (int j = 0; j < 8; j++) {
            float rx = 0.f, ry = 0.f;
#pragma unroll
            for (int t = 0; t < 4; t++) {
                float2 a = unpack2(acc[t][j]);
                rx += fmaxf(a.x, 0.f);
                ry += fmaxf(a.y, 0.f);
            }
            g_poolT[(size_t)(16 * h + 2 * j) * F + face] = rx * 0.25f;
            g_poolT[(size_t)(16 * h + 2 * j + 1) * F + face] = ry * 0.25f;
        }
    }
}

// ---------------------------------------------------------------------------
// K3: fco GEMM. Thread = 4 faces x 16 cols; block = 256 faces.
__global__ void __launch_bounds__(128)
fco_kernel(const float* __restrict__ fco_w, const float* __restrict__ fco_b,
           float* __restrict__ out, int F) {
    __shared__ __align__(16) float ws[1024];
    __shared__ __align__(16) float bs[32];
    int tid = threadIdx.x;
    for (int i = tid; i < 1024; i += 128) ws[i] = fco_w[i];
    if (tid < 32) bs[tid] = fco_b[tid];
    __syncthreads();

    int fg = tid >> 1;      // 0..63
    int half = tid & 1;
    int fbase = blockIdx.x * 256 + fg;

    int fidx[4];
#pragma unroll
    for (int i = 0; i < 4; i++) {
        int f = fbase + 64 * i;
        fidx[i] = (f < F) ? f : (F - 1);
    }

    u64 acc[4][8];
    {
        const u64* bb = (const u64*)(bs + 16 * half);
#pragma unroll
        for (int i = 0; i < 4; i++)
#pragma unroll
            for (int j = 0; j < 8; j++) acc[i][j] = bb[j];
    }

#pragma unroll
    for (int k = 0; k < 32; k++) {
        const ulonglong2* wr = (const ulonglong2*)(ws + k * 32 + 16 * half);
        ulonglong2 wa = wr[0], wb = wr[1], wc = wr[2], wd = wr[3];
        const float* pk = g_poolT + (size_t)k * F;
#pragma unroll
        for (int i = 0; i < 4; i++) {
            float a = pk[fidx[i]];
            u64 ap = pack2(a, a);
            acc[i][0] = fma2(ap, wa.x, acc[i][0]);
            acc[i][1] = fma2(ap, wa.y, acc[i][1]);
            acc[i][2] = fma2(ap, wb.x, acc[i][2]);
            acc[i][3] = fma2(ap, wb.y, acc[i][3]);
            acc[i][4] = fma2(ap, wc.x, acc[i][4]);
            acc[i][5] = fma2(ap, wc.y, acc[i][5]);
            acc[i][6] = fma2(ap, wd.x, acc[i][6]);
            acc[i][7] = fma2(ap, wd.y, acc[i][7]);
        }
    }

#pragma unroll
    for (int i = 0; i < 4; i++) {
        int f = fbase + 64 * i;
        if (f < F) {
            float* op = out + (size_t)f * 32 + 16 * half;
#pragma unroll
            for (int j = 0; j < 4; j++) {
                float2 a = unpack2(acc[i][2 * j]);
                float2 b = unpack2(acc[i][2 * j + 1]);
                ((float4*)op)[j] = make_float4(a.x, a.y, b.x, b.y);
            }
        }
    }
}

// ---------------------------------------------------------------------------
extern "C" void kernel_launch(void* const* d_in, const int* in_sizes, int n_in,
                              void* d_out, int out_size) {
    const float* node  = (const float*)d_in[0];
    const int*   fids  = (const int*)d_in[1];
    const float* w_in  = (const float*)d_in[2];
    const float* b_in  = (const float*)d_in[3];
    const float* w_out = (const float*)d_in[4];
    const float* b_out = (const float*)d_in[5];
    const float* fc_w  = (const float*)d_in[6];
    const float* fc_b  = (const float*)d_in[7];
    const float* fco_w = (const float*)d_in[8];
    const float* fco_b = (const float*)d_in[9];

    int Nn = in_sizes[0] / 16;   // 250000
    int F  = in_sizes[1] / 4;    // 500000

    prep_kernel<<<1, 512>>>(w_out, b_out, fc_w, fc_b);
    qkv_kernel<<<(Nn + 127) / 128, 128>>>(node, w_in, b_in, Nn);
    face_kernel<<<(F + 63) / 64, 128>>>(fids, F);
    fco_kernel<<<(F + 255) / 256, 128>>>(fco_w, fco_b, (float*)d_out, F);
}

// round 7
// speedup vs baseline: 2.2210x; 2.2210x over previous
#include <cuda_runtime.h>

// PlaneEmbeddingNetwork fused kernel for GB300 (sm_103a), R7.
// = R2 (best: 151us) + column-split W2 and fco phases.
// 2 threads per face (one per head), adjacent lanes, lane-local token order.
// W2: each thread computes cols [16h,16h+16) for ALL 4 tokens (weights
// amortized over 4 tokens instead of 2; pool becomes thread-local).
// fco: each thread computes out cols [16h,16h+16) after an 8-shuffle pooled
// exchange (halves both the weight LDS and the FMA of that phase).

typedef unsigned long long u64;

__device__ __forceinline__ u64 fma2(u64 a, u64 b, u64 c) {
    u64 d;
    asm("fma.rn.f32x2 %0, %1, %2, %3;" : "=l"(d) : "l"(a), "l"(b), "l"(c));
    return d;
}
__device__ __forceinline__ u64 pack2(float x, float y) {
    u64 r;
    asm("mov.b64 %0, {%1, %2};" : "=l"(r) : "f"(x), "f"(y));
    return r;
}
__device__ __forceinline__ float2 unpack2(u64 v) {
    float2 f;
    asm("mov.b64 {%0, %1}, %2;" : "=f"(f.x), "=f"(f.y) : "l"(v));
    return f;
}
__device__ __forceinline__ float getc(float4 v, int c) {
    return c == 0 ? v.x : (c == 1 ? v.y : (c == 2 ? v.z : v.w));
}

// Fused weights computed once by prep kernel:
//   W2[d][j] = sum_e w_out[d][e] * fc_w[e][j]    (16 x 32)
//   b2[j]    = fc_b[j] + sum_e b_out[e] * fc_w[e][j]
__device__ float g_W2[16 * 32];
__device__ float g_b2[32];

__global__ void prep_kernel(const float* __restrict__ w_out, const float* __restrict__ b_out,
                            const float* __restrict__ fc_w, const float* __restrict__ fc_b) {
    int i = threadIdx.x;
    if (i < 512) {
        int d = i >> 5, j = i & 31;
        float s = 0.f;
#pragma unroll
        for (int e = 0; e < 16; e++) s += w_out[d * 16 + e] * fc_w[e * 32 + j];
        g_W2[i] = s;
    }
    if (i < 32) {
        float s = fc_b[i];
#pragma unroll
        for (int e = 0; e < 16; e++) s += b_out[e] * fc_w[e * 32 + i];
        g_b2[i] = s;
    }
}

__global__ void __launch_bounds__(128, 4)
face_kernel(const float* __restrict__ node, const int* __restrict__ fids,
            const float* __restrict__ w_in, const float* __restrict__ b_in,
            const float* __restrict__ fco_w, const float* __restrict__ fco_b,
            float* __restrict__ out, int F) {
    __shared__ __align__(16) float s_win[16 * 48];   // packed qkv weights [d][o]
    __shared__ __align__(16) float s_bin[48];
    __shared__ __align__(16) float s_W2[16 * 32];    // fused w_out@fc_w
    __shared__ __align__(16) float s_b2[32];
    __shared__ __align__(16) float s_fco[32 * 32];
    __shared__ __align__(16) float s_fcob[32];

    int tid = threadIdx.x;
    for (int i = tid; i < 768; i += 128) s_win[i] = w_in[i];
    if (tid < 48) s_bin[tid] = b_in[tid];
    for (int i = tid; i < 512; i += 128) s_W2[i] = g_W2[i];
    if (tid < 32) s_b2[tid] = g_b2[tid];
    for (int i = tid; i < 1024; i += 128) s_fco[i] = fco_w[i];
    if (tid < 32) s_fcob[tid] = fco_b[tid];
    __syncthreads();

    int gt = blockIdx.x * 128 + tid;
    int face = gt >> 1;
    int h = gt & 1;                 // head index (0 or 1)
    bool valid = face < F;
    if (!valid) face = F - 1;       // clamp: tail lanes still participate in shuffles

    // ---- gather: each lane loads only its OWN 2 tokens (lane-local order) ----
    int4 I = *(const int4*)(fids + 4ll * face);
    int ida = h ? I.z : I.x;
    int idb = h ? I.w : I.y;
    float4 XA[4], XB[4];
    {
        const float4* ra = (const float4*)(node + 16ll * ida);
        const float4* rb = (const float4*)(node + 16ll * idb);
        XA[0] = ra[0]; XA[1] = ra[1]; XA[2] = ra[2]; XA[3] = ra[3];
        XB[0] = rb[0]; XB[1] = rb[1]; XB[2] = rb[2]; XB[3] = rb[3];
    }

    // Lane-local token order: 0 = own_a, 1 = own_b, 2 = partner_a, 3 = partner_b.
    // Attention is permutation-invariant per head, so lanes may disagree on order.

    // ---- phase 1a: q,k for all 4 tokens (own head), d-outer for weight reuse ----
    u64 q2[4][4], k2[4][4];
    {
        const u64* bq = (const u64*)(s_bin + 8 * h);
        const u64* bk = (const u64*)(s_bin + 16 + 8 * h);
#pragma unroll
        for (int t = 0; t < 4; t++)
#pragma unroll
            for (int j = 0; j < 4; j++) { q2[t][j] = bq[j]; k2[t][j] = bk[j]; }
    }
    {
        const float* wq = s_win + 8 * h;
        const float* wk = s_win + 16 + 8 * h;
#pragma unroll
        for (int d = 0; d < 16; d++) {
            ulonglong2 wq0 = *(const ulonglong2*)(wq + d * 48);
            ulonglong2 wq1 = *(const ulonglong2*)(wq + d * 48 + 4);
            ulonglong2 wk0 = *(const ulonglong2*)(wk + d * 48);
            ulonglong2 wk1 = *(const ulonglong2*)(wk + d * 48 + 4);
            float xa = getc(XA[d >> 2], d & 3);
            float xb = getc(XB[d >> 2], d & 3);
            float fa = __shfl_xor_sync(0xffffffffu, xa, 1);
            float fb = __shfl_xor_sync(0xffffffffu, xb, 1);
            u64 xt[4] = {pack2(xa, xa), pack2(xb, xb), pack2(fa, fa), pack2(fb, fb)};
#pragma unroll
            for (int t = 0; t < 4; t++) {
                q2[t][0] = fma2(xt[t], wq0.x, q2[t][0]);
                q2[t][1] = fma2(xt[t], wq0.y, q2[t][1]);
                q2[t][2] = fma2(xt[t], wq1.x, q2[t][2]);
                q2[t][3] = fma2(xt[t], wq1.y, q2[t][3]);
                k2[t][0] = fma2(xt[t], wk0.x, k2[t][0]);
                k2[t][1] = fma2(xt[t], wk0.y, k2[t][1]);
                k2[t][2] = fma2(xt[t], wk1.x, k2[t][2]);
                k2[t][3] = fma2(xt[t], wk1.y, k2[t][3]);
            }
        }
    }

    // ---- scores + softmax (own head, 4x4, lane-local token order) ----
    float att[4][4];
    const float RS = 0.35355339059327373f;  // 1/sqrt(8)
#pragma unroll
    for (int qi = 0; qi < 4; qi++) {
#pragma unroll
        for (int ki = 0; ki < 4; ki++) {
            u64 a = fma2(q2[qi][0], k2[ki][0], 0ull);
            a = fma2(q2[qi][1], k2[ki][1], a);
            a = fma2(q2[qi][2], k2[ki][2], a);
            a = fma2(q2[qi][3], k2[ki][3], a);
            float2 p = unpack2(a);
            att[qi][ki] = (p.x + p.y) * RS;
        }
        float m = fmaxf(fmaxf(att[qi][0], att[qi][1]), fmaxf(att[qi][2], att[qi][3]));
        float e0 = __expf(att[qi][0] - m);
        float e1 = __expf(att[qi][1] - m);
        float e2 = __expf(att[qi][2] - m);
        float e3 = __expf(att[qi][3] - m);
        float inv = 1.0f / (e0 + e1 + e2 + e3);
        att[qi][0] = e0 * inv; att[qi][1] = e1 * inv;
        att[qi][2] = e2 * inv; att[qi][3] = e3 * inv;
    }

    // ---- phase 1b: v for all 4 tokens (own head), d-outer ----
    u64 v2[4][4];
    {
        const u64* bv = (const u64*)(s_bin + 32 + 8 * h);
#pragma unroll
        for (int t = 0; t < 4; t++)
#pragma unroll
            for (int j = 0; j < 4; j++) v2[t][j] = bv[j];
    }
    {
        const float* wv = s_win + 32 + 8 * h;
#pragma unroll
        for (int d = 0; d < 16; d++) {
            ulonglong2 wv0 = *(const ulonglong2*)(wv + d * 48);
            ulonglong2 wv1 = *(const ulonglong2*)(wv + d * 48 + 4);
            float xa = getc(XA[d >> 2], d & 3);
            float xb = getc(XB[d >> 2], d & 3);
            float fa = __shfl_xor_sync(0xffffffffu, xa, 1);
            float fb = __shfl_xor_sync(0xffffffffu, xb, 1);
            u64 xt[4] = {pack2(xa, xa), pack2(xb, xb), pack2(fa, fa), pack2(fb, fb)};
#pragma unroll
            for (int t = 0; t < 4; t++) {
                v2[t][0] = fma2(xt[t], wv0.x, v2[t][0]);
                v2[t][1] = fma2(xt[t], wv0.y, v2[t][1]);
                v2[t][2] = fma2(xt[t], wv1.x, v2[t][2]);
                v2[t][3] = fma2(xt[t], wv1.y, v2[t][3]);
            }
        }
    }

    // ---- o = attn @ v for all 4 local query tokens (own head half: 8 dims) ----
    u64 o2[4][4];
#pragma unroll
    for (int qi = 0; qi < 4; qi++) {
#pragma unroll
        for (int j = 0; j < 4; j++) o2[qi][j] = 0ull;
#pragma unroll
        for (int s = 0; s < 4; s++) {
            u64 a2 = pack2(att[qi][s], att[qi][s]);
#pragma unroll
            for (int j = 0; j < 4; j++) o2[qi][j] = fma2(a2, v2[s][j], o2[qi][j]);
        }
    }

    // ---- exchange o for ALL 4 local tokens. Partner's local index of my
    //      token t is t^2 (its tokens 0,1 are my 2,3 and vice versa). ----
    u64 lo[4][4], hi[4][4];   // full o: dims 0-7 (head0) and 8-15 (head1)
#pragma unroll
    for (int t = 0; t < 4; t++)
#pragma unroll
        for (int j = 0; j < 4; j++) {
            u64 rcv = __shfl_xor_sync(0xffffffffu, o2[t ^ 2][j], 1);
            lo[t][j] = h ? rcv : o2[t][j];
            hi[t][j] = h ? o2[t][j] : rcv;
        }

    // ---- W2 col-split: cols [16h,16h+16) for ALL 4 tokens ----
    u64 acc[4][8];
    {
        const u64* bb = (const u64*)(s_b2 + 16 * h);
#pragma unroll
        for (int t = 0; t < 4; t++)
#pragma unroll
            for (int j = 0; j < 8; j++) acc[t][j] = bb[j];
    }
#pragma unroll
    for (int d = 0; d < 16; d++) {
        const ulonglong2* wr = (const ulonglong2*)(s_W2 + d * 32 + 16 * h);
        ulonglong2 wa = wr[0], wb = wr[1], wc = wr[2], wd_ = wr[3];
#pragma unroll
        for (int t = 0; t < 4; t++) {
            float ov;
            if (d < 8) {
                float2 p = unpack2(lo[t][d >> 1]);
                ov = (d & 1) ? p.y : p.x;
            } else {
                float2 p = unpack2(hi[t][(d - 8) >> 1]);
                ov = (d & 1) ? p.y : p.x;
            }
            u64 op = pack2(ov, ov);
            acc[t][0] = fma2(op, wa.x, acc[t][0]);
            acc[t][1] = fma2(op, wa.y, acc[t][1]);
            acc[t][2] = fma2(op, wb.x, acc[t][2]);
            acc[t][3] = fma2(op, wb.y, acc[t][3]);
            acc[t][4] = fma2(op, wc.x, acc[t][4]);
            acc[t][5] = fma2(op, wc.y, acc[t][5]);
            acc[t][6] = fma2(op, wd_.x, acc[t][6]);
            acc[t][7] = fma2(op, wd_.y, acc[t][7]);
        }
    }

    // ---- relu + mean over 4 tokens (thread-local: pooling is order-invariant) ----
    u64 pool[8];   // my 16 cols
#pragma unroll
    for (int j = 0; j < 8; j++) {
        float px = 0.f, py = 0.f;
#pragma unroll
        for (int t = 0; t < 4; t++) {
            float2 a = unpack2(acc[t][j]);
            px += fmaxf(a.x, 0.f);
            py += fmaxf(a.y, 0.f);
        }
        pool[j] = pack2(px * 0.25f, py * 0.25f);
    }

    // ---- exchange pooled halves -> full 32 cols ----
    u64 pa[16];
#pragma unroll
    for (int j = 0; j < 8; j++) {
        u64 other = __shfl_xor_sync(0xffffffffu, pool[j], 1);
        pa[j]     = h ? other : pool[j];
        pa[8 + j] = h ? pool[j] : other;
    }

    // ---- fco col-split: out cols [16h,16h+16) ----
    u64 acc2[8];
    {
        const u64* fb = (const u64*)(s_fcob + 16 * h);
#pragma unroll
        for (int p = 0; p < 8; p++) acc2[p] = fb[p];
    }
#pragma unroll
    for (int e = 0; e < 32; e++) {
        float2 pp = unpack2(pa[e >> 1]);
        float pe = (e & 1) ? pp.y : pp.x;
        u64 pe2 = pack2(pe, pe);
        const ulonglong2* fr = (const ulonglong2*)(s_fco + e * 32 + 16 * h);
        ulonglong2 wa = fr[0], wb = fr[1], wc = fr[2], wd_ = fr[3];
        acc2[0] = fma2(pe2, wa.x, acc2[0]);
        acc2[1] = fma2(pe2, wa.y, acc2[1]);
        acc2[2] = fma2(pe2, wb.x, acc2[2]);
        acc2[3] = fma2(pe2, wb.y, acc2[3]);
        acc2[4] = fma2(pe2, wc.x, acc2[4]);
        acc2[5] = fma2(pe2, wc.y, acc2[5]);
        acc2[6] = fma2(pe2, wd_.x, acc2[6]);
        acc2[7] = fma2(pe2, wd_.y, acc2[7]);
    }

    if (valid) {
        float* op = out + 32ll * face + 16 * h;
#pragma unroll
        for (int p4 = 0; p4 < 4; p4++) {
            float2 a = unpack2(acc2[2 * p4]);
            float2 b = unpack2(acc2[2 * p4 + 1]);
            *(float4*)(op + 4 * p4) = make_float4(a.x, a.y, b.x, b.y);
        }
    }
}

extern "C" void kernel_launch(void* const* d_in, const int* in_sizes, int n_in,
                              void* d_out, int out_size) {
    const float* node  = (const float*)d_in[0];
    const int*   fids  = (const int*)d_in[1];
    const float* w_in  = (const float*)d_in[2];
    const float* b_in  = (const float*)d_in[3];
    const float* w_out = (const float*)d_in[4];
    const float* b_out = (const float*)d_in[5];
    const float* fc_w  = (const float*)d_in[6];
    const float* fc_b  = (const float*)d_in[7];
    const float* fco_w = (const float*)d_in[8];
    const float* fco_b = (const float*)d_in[9];

    int F = in_sizes[1] / 4;

    prep_kernel<<<1, 512>>>(w_out, b_out, fc_w, fc_b);

    long long threads = 2ll * F;
    int blocks = (int)((threads + 127) / 128);
    face_kernel<<<blocks, 128>>>(node, fids, w_in, b_in, fco_w, fco_b, (float*)d_out, F);
}